// round 9
// baseline (speedup 1.0000x reference)
#include <cuda_runtime.h>
#include <math.h>

#define V_MAX   100000
#define E_MAX   1600000
#define IN_CH   128
#define HEADS   4
#define HC      64
#define NEG_SLOPE 0.2f
#define SCAN_BLK 256
#define TROWS   32              // gemm tile rows (halved for occupancy)

// ---------------- scratch (device globals; no allocation) ----------------
__device__ float g_z[(size_t)V_MAX * HC];     // projected features  [V,64]
__device__ float g_esrc[V_MAX * HEADS];       // per-node src logits [V,4]
__device__ float g_edst[V_MAX * HEADS];       // per-node dst logits [V,4]
__device__ int   g_deg[V_MAX];                // in-degree per node
__device__ int   g_excl[V_MAX];               // block-local exclusive scan
__device__ int   g_bsums[512];                // per-block sums
__device__ int   g_rowstart[V_MAX];           // CSR row offsets
__device__ int   g_cursor[V_MAX];             // scatter cursors
__device__ int   g_csr_src[E_MAX];            // src node per CSR slot

// ---------------- CSR build ----------------
__global__ void zero_deg_kernel(int v) {
    int i = blockIdx.x * blockDim.x + threadIdx.x;
    if (i < v) g_deg[i] = 0;
}

__global__ void count_kernel(const int* __restrict__ ei, int ecnt) {
    int e = blockIdx.x * blockDim.x + threadIdx.x;
    if (e < ecnt) atomicAdd(&g_deg[ei[ecnt + e]], 1);
}

__global__ void scan1_kernel(int v) {
    __shared__ int sh[SCAN_BLK];
    int t = threadIdx.x;
    int i = blockIdx.x * SCAN_BLK + t;
    int val = (i < v) ? g_deg[i] : 0;
    sh[t] = val;
    __syncthreads();
#pragma unroll
    for (int off = 1; off < SCAN_BLK; off <<= 1) {
        int y = (t >= off) ? sh[t - off] : 0;
        __syncthreads();
        sh[t] += y;
        __syncthreads();
    }
    if (i < v) g_excl[i] = sh[t] - val;
    if (t == SCAN_BLK - 1) g_bsums[blockIdx.x] = sh[t];
}

__global__ void scan3_kernel(int v) {
    __shared__ int red[SCAN_BLK];
    const int b = blockIdx.x;
    const int t = threadIdx.x;
    int sum = 0;
    for (int i = t; i < b; i += SCAN_BLK) sum += g_bsums[i];
    red[t] = sum;
    __syncthreads();
#pragma unroll
    for (int off = SCAN_BLK / 2; off; off >>= 1) {
        if (t < off) red[t] += red[t + off];
        __syncthreads();
    }
    int prefix = red[0];
    int i = b * SCAN_BLK + t;
    if (i < v) {
        int r = g_excl[i] + prefix;
        g_rowstart[i] = r;
        g_cursor[i]   = r;
    }
}

__global__ void scatter_kernel(const int* __restrict__ ei, int ecnt) {
    int e = blockIdx.x * blockDim.x + threadIdx.x;
    if (e >= ecnt) return;
    int s = ei[e];
    int d = ei[ecnt + e];
    int pos = atomicAdd(&g_cursor[d], 1);
    g_csr_src[pos] = s;
}

// ---------------- fused GEMM + logits (32-row tile, 4 blocks/SM) ---------
// smem 49KB -> occ 50% (vs 34%); thread tile 2 rows x 4 cols.
__global__ void gemm_logits_kernel(const float* __restrict__ x,
                                   const float* __restrict__ W,
                                   const float* __restrict__ a_src,
                                   const float* __restrict__ a_dst,
                                   int v)
{
    extern __shared__ float sm[];
    float* Ws = sm;                       // 128*64
    float* xs = Ws + IN_CH * HC;          // TROWS * 132
    float* as = xs + TROWS * 132;         // 64
    float* ad = as + 64;                  // 64

    const int tx = threadIdx.x, ty = threadIdx.y;
    const int tid = ty * 16 + tx;
    const int row0 = blockIdx.x * TROWS;

    for (int i = tid; i < (IN_CH * HC) / 4; i += 256)
        ((float4*)Ws)[i] = ((const float4*)W)[i];
    if (tid < 64)       as[tid]      = a_src[tid];
    else if (tid < 128) ad[tid - 64] = a_dst[tid - 64];

    for (int i = tid; i < TROWS * 32; i += 256) {
        int r = i >> 5, c4 = i & 31;
        float4 val = make_float4(0.f, 0.f, 0.f, 0.f);
        if (row0 + r < v)
            val = ((const float4*)x)[(size_t)(row0 + r) * 32 + c4];
        *(float4*)&xs[r * 132 + c4 * 4] = val;
    }
    __syncthreads();

    float acc[2][4];
#pragma unroll
    for (int i = 0; i < 2; ++i)
#pragma unroll
        for (int j = 0; j < 4; ++j) acc[i][j] = 0.f;

#pragma unroll 4
    for (int k0 = 0; k0 < IN_CH; k0 += 4) {
        float4 xv[2];
#pragma unroll
        for (int i = 0; i < 2; ++i)
            xv[i] = *(const float4*)&xs[(ty * 2 + i) * 132 + k0];
#pragma unroll
        for (int kk = 0; kk < 4; ++kk) {
            float4 wv = ((float4*)Ws)[(k0 + kk) * 16 + tx];
#pragma unroll
            for (int i = 0; i < 2; ++i) {
                float xk = kk == 0 ? xv[i].x : kk == 1 ? xv[i].y
                         : kk == 2 ? xv[i].z : xv[i].w;
                acc[i][0] += xk * wv.x;
                acc[i][1] += xk * wv.y;
                acc[i][2] += xk * wv.z;
                acc[i][3] += xk * wv.w;
            }
        }
    }

    const int h  = tx >> 2;
    const int c0 = (tx & 3) * 4;
#pragma unroll
    for (int i = 0; i < 2; ++i) {
        int row = row0 + ty * 2 + i;
        float ps = acc[i][0] * as[h * 16 + c0 + 0] + acc[i][1] * as[h * 16 + c0 + 1]
                 + acc[i][2] * as[h * 16 + c0 + 2] + acc[i][3] * as[h * 16 + c0 + 3];
        float pd = acc[i][0] * ad[h * 16 + c0 + 0] + acc[i][1] * ad[h * 16 + c0 + 1]
                 + acc[i][2] * ad[h * 16 + c0 + 2] + acc[i][3] * ad[h * 16 + c0 + 3];
        ps += __shfl_xor_sync(0xffffffffu, ps, 1);
        ps += __shfl_xor_sync(0xffffffffu, ps, 2);
        pd += __shfl_xor_sync(0xffffffffu, pd, 1);
        pd += __shfl_xor_sync(0xffffffffu, pd, 2);

        if (row < v) {
            *(float4*)&g_z[(size_t)row * HC + tx * 4] =
                make_float4(acc[i][0], acc[i][1], acc[i][2], acc[i][3]);
            if ((tx & 3) == 0) {
                g_esrc[row * HEADS + h] = ps;
                g_edst[row * HEADS + h] = pd;
            }
        }
    }
}

// ---------------- fused softmax + aggregation (CSR, smem-staged) ----------
__global__ void node_agg_kernel(float* __restrict__ out, int v) {
    __shared__ int   sh_s[8][32];
    __shared__ float sh_a[8][32][4];

    const int wid  = threadIdx.x >> 5;
    const int lane = threadIdx.x & 31;
    const int n = blockIdx.x * 8 + wid;
    if (n >= v) return;

    const int start = g_rowstart[n];
    const int degn  = g_deg[n];
    const float4 ed = *(const float4*)&g_edst[n * 4];
    const int head  = lane >> 3;

    float acc0 = 0.f, acc1 = 0.f;
    float d0 = 0.f, d1 = 0.f, d2 = 0.f, d3 = 0.f;

    for (int i0 = 0; i0 < degn; i0 += 32) {
        int idx = i0 + lane;
        int s = 0;
        float ex0 = 0.f, ex1 = 0.f, ex2 = 0.f, ex3 = 0.f;
        if (idx < degn) {
            s = __ldg(&g_csr_src[start + idx]);
            float4 es = *(const float4*)&g_esrc[s * 4];
            float w;
            w = es.x + ed.x; w = w > 0.f ? w : NEG_SLOPE * w; ex0 = __expf(w);
            w = es.y + ed.y; w = w > 0.f ? w : NEG_SLOPE * w; ex1 = __expf(w);
            w = es.z + ed.z; w = w > 0.f ? w : NEG_SLOPE * w; ex2 = __expf(w);
            w = es.w + ed.w; w = w > 0.f ? w : NEG_SLOPE * w; ex3 = __expf(w);
        }
        d0 += ex0; d1 += ex1; d2 += ex2; d3 += ex3;
        sh_s[wid][lane] = s;
        *(float4*)&sh_a[wid][lane][0] = make_float4(ex0, ex1, ex2, ex3);
        __syncwarp();

        int cnt = degn - i0; if (cnt > 32) cnt = 32;
        const float* zb = g_z + (size_t)lane * 2;
        int j = 0;
        for (; j + 8 <= cnt; j += 8) {
            int    sj[8];
            float2 zj[8];
            float  aj[8];
#pragma unroll
            for (int u = 0; u < 8; ++u) sj[u] = sh_s[wid][j + u];
#pragma unroll
            for (int u = 0; u < 8; ++u) zj[u] = *(const float2*)(zb + (size_t)sj[u] * HC);
#pragma unroll
            for (int u = 0; u < 8; ++u) aj[u] = sh_a[wid][j + u][head];
#pragma unroll
            for (int u = 0; u < 8; ++u) {
                acc0 += zj[u].x * aj[u];
                acc1 += zj[u].y * aj[u];
            }
        }
        for (; j < cnt; ++j) {
            int sj = sh_s[wid][j];
            float a = sh_a[wid][j][head];
            float2 zv = *(const float2*)(zb + (size_t)sj * HC);
            acc0 += zv.x * a; acc1 += zv.y * a;
        }
        __syncwarp();
    }

#pragma unroll
    for (int o = 16; o; o >>= 1) {
        d0 += __shfl_xor_sync(0xffffffffu, d0, o);
        d1 += __shfl_xor_sync(0xffffffffu, d1, o);
        d2 += __shfl_xor_sync(0xffffffffu, d2, o);
        d3 += __shfl_xor_sync(0xffffffffu, d3, o);
    }
    float den = head == 0 ? d0 : head == 1 ? d1 : head == 2 ? d2 : d3;
    float r = __frcp_rn(den + 1e-9f);
    acc0 *= r; acc1 *= r;
    acc0 = acc0 > 0.f ? acc0 : expm1f(acc0);
    acc1 = acc1 > 0.f ? acc1 : expm1f(acc1);
    *(float2*)&out[(size_t)n * HC + lane * 2] = make_float2(acc0, acc1);
}

// ---------------- launch ----------------
// gemm stays launch #4 so ncu keeps profiling it.
extern "C" void kernel_launch(void* const* d_in, const int* in_sizes, int n_in,
                              void* d_out, int out_size) {
    const float* x     = (const float*)d_in[0];
    const int*   ei    = (const int*)d_in[1];
    const float* W     = (const float*)d_in[2];
    const float* a_src = (const float*)d_in[3];
    const float* a_dst = (const float*)d_in[4];
    float* out = (float*)d_out;

    int v    = in_sizes[0] / IN_CH;
    int ecnt = in_sizes[1] / 2;
    int nb   = (v + SCAN_BLK - 1) / SCAN_BLK;

    const int smem = (IN_CH * HC + TROWS * 132 + 128) * sizeof(float); // ~49.5KB
    cudaFuncSetAttribute(gemm_logits_kernel,
                         cudaFuncAttributeMaxDynamicSharedMemorySize, smem);

    zero_deg_kernel<<<(v + 255) / 256, 256>>>(v);
    count_kernel<<<(ecnt + 255) / 256, 256>>>(ei, ecnt);
    scan1_kernel<<<nb, SCAN_BLK>>>(v);
    gemm_logits_kernel<<<(v + TROWS - 1) / TROWS, dim3(16, 16), smem>>>(x, W, a_src, a_dst, v);
    scan3_kernel<<<nb, SCAN_BLK>>>(v);
    scatter_kernel<<<(ecnt + 255) / 256, 256>>>(ei, ecnt);
    node_agg_kernel<<<(v + 7) / 8, 256>>>(out, v);
}

// round 10
// speedup vs baseline: 1.0985x; 1.0985x over previous
#include <cuda_runtime.h>
#include <math.h>

#define V_MAX   100000
#define E_MAX   1600000
#define IN_CH   128
#define HEADS   4
#define HC      64
#define NEG_SLOPE 0.2f
#define SCAN_BLK 256
#define TROWS   128             // gemm tile rows
#define TTHREADS 512            // gemm block threads (16 x 32)

// ---------------- scratch (device globals; no allocation) ----------------
__device__ float g_z[(size_t)V_MAX * HC];     // projected features  [V,64]
__device__ float g_esrc[V_MAX * HEADS];       // per-node src logits [V,4]
__device__ float g_edst[V_MAX * HEADS];       // per-node dst logits [V,4]
__device__ int   g_deg[V_MAX];                // in-degree per node
__device__ int   g_excl[V_MAX];               // block-local exclusive scan
__device__ int   g_bsums[512];                // per-block sums
__device__ int   g_rowstart[V_MAX];           // CSR row offsets
__device__ int   g_cursor[V_MAX];             // scatter cursors
__device__ int   g_csr_src[E_MAX];            // src node per CSR slot

// ---------------- CSR build ----------------
__global__ void zero_deg_kernel(int v) {
    int i = blockIdx.x * blockDim.x + threadIdx.x;
    if (i < v) g_deg[i] = 0;
}

__global__ void count_kernel(const int* __restrict__ ei, int ecnt) {
    int e = blockIdx.x * blockDim.x + threadIdx.x;
    if (e < ecnt) atomicAdd(&g_deg[ei[ecnt + e]], 1);
}

__global__ void scan1_kernel(int v) {
    __shared__ int sh[SCAN_BLK];
    int t = threadIdx.x;
    int i = blockIdx.x * SCAN_BLK + t;
    int val = (i < v) ? g_deg[i] : 0;
    sh[t] = val;
    __syncthreads();
#pragma unroll
    for (int off = 1; off < SCAN_BLK; off <<= 1) {
        int y = (t >= off) ? sh[t - off] : 0;
        __syncthreads();
        sh[t] += y;
        __syncthreads();
    }
    if (i < v) g_excl[i] = sh[t] - val;
    if (t == SCAN_BLK - 1) g_bsums[blockIdx.x] = sh[t];
}

__global__ void scan3_kernel(int v) {
    __shared__ int red[SCAN_BLK];
    const int b = blockIdx.x;
    const int t = threadIdx.x;
    int sum = 0;
    for (int i = t; i < b; i += SCAN_BLK) sum += g_bsums[i];
    red[t] = sum;
    __syncthreads();
#pragma unroll
    for (int off = SCAN_BLK / 2; off; off >>= 1) {
        if (t < off) red[t] += red[t + off];
        __syncthreads();
    }
    int prefix = red[0];
    int i = b * SCAN_BLK + t;
    if (i < v) {
        int r = g_excl[i] + prefix;
        g_rowstart[i] = r;
        g_cursor[i]   = r;
    }
}

__global__ void scatter_kernel(const int* __restrict__ ei, int ecnt) {
    int e = blockIdx.x * blockDim.x + threadIdx.x;
    if (e >= ecnt) return;
    int s = ei[e];
    int d = ei[ecnt + e];
    int pos = atomicAdd(&g_cursor[d], 1);
    g_csr_src[pos] = s;
}

// ---------------- fused GEMM + logits (128-row tile, 512 threads) --------
// W staged once per 128 rows (halves staging traffic vs 64-row tile) and
// 2 blocks/SM = 32 warps (occ 50% vs 34%). Inner loop identical to the
// proven R7 version: thread tile 4 rows x 4 cols.
__global__ void __launch_bounds__(TTHREADS, 2)
gemm_logits_kernel(const float* __restrict__ x,
                   const float* __restrict__ W,
                   const float* __restrict__ a_src,
                   const float* __restrict__ a_dst,
                   int v)
{
    extern __shared__ float sm[];
    float* Ws = sm;                       // 128*64
    float* xs = Ws + IN_CH * HC;          // TROWS * 132
    float* as = xs + TROWS * 132;         // 64
    float* ad = as + 64;                  // 64

    const int tx = threadIdx.x, ty = threadIdx.y;   // (16, 32)
    const int tid = ty * 16 + tx;
    const int row0 = blockIdx.x * TROWS;

    for (int i = tid; i < (IN_CH * HC) / 4; i += TTHREADS)
        ((float4*)Ws)[i] = ((const float4*)W)[i];
    if (tid < 64)       as[tid]      = a_src[tid];
    else if (tid < 128) ad[tid - 64] = a_dst[tid - 64];

    for (int i = tid; i < TROWS * 32; i += TTHREADS) {
        int r = i >> 5, c4 = i & 31;
        float4 val = make_float4(0.f, 0.f, 0.f, 0.f);
        if (row0 + r < v)
            val = ((const float4*)x)[(size_t)(row0 + r) * 32 + c4];
        *(float4*)&xs[r * 132 + c4 * 4] = val;
    }
    __syncthreads();

    float acc[4][4];
#pragma unroll
    for (int i = 0; i < 4; ++i)
#pragma unroll
        for (int j = 0; j < 4; ++j) acc[i][j] = 0.f;

#pragma unroll 8
    for (int k = 0; k < IN_CH; ++k) {
        float4 wv = ((float4*)Ws)[k * 16 + tx];
#pragma unroll
        for (int i = 0; i < 4; ++i) {
            float xv = xs[(ty * 4 + i) * 132 + k];
            acc[i][0] += xv * wv.x;
            acc[i][1] += xv * wv.y;
            acc[i][2] += xv * wv.z;
            acc[i][3] += xv * wv.w;
        }
    }

    const int h  = tx >> 2;
    const int c0 = (tx & 3) * 4;
#pragma unroll
    for (int i = 0; i < 4; ++i) {
        int row = row0 + ty * 4 + i;
        float ps = acc[i][0] * as[h * 16 + c0 + 0] + acc[i][1] * as[h * 16 + c0 + 1]
                 + acc[i][2] * as[h * 16 + c0 + 2] + acc[i][3] * as[h * 16 + c0 + 3];
        float pd = acc[i][0] * ad[h * 16 + c0 + 0] + acc[i][1] * ad[h * 16 + c0 + 1]
                 + acc[i][2] * ad[h * 16 + c0 + 2] + acc[i][3] * ad[h * 16 + c0 + 3];
        // lane = (ty&1)*16 + tx, so xor 1/2 stays within the tx&3 quad
        ps += __shfl_xor_sync(0xffffffffu, ps, 1);
        ps += __shfl_xor_sync(0xffffffffu, ps, 2);
        pd += __shfl_xor_sync(0xffffffffu, pd, 1);
        pd += __shfl_xor_sync(0xffffffffu, pd, 2);

        if (row < v) {
            *(float4*)&g_z[(size_t)row * HC + tx * 4] =
                make_float4(acc[i][0], acc[i][1], acc[i][2], acc[i][3]);
            if ((tx & 3) == 0) {
                g_esrc[row * HEADS + h] = ps;
                g_edst[row * HEADS + h] = pd;
            }
        }
    }
}

// ---------------- fused softmax + aggregation (CSR, smem-staged) ----------
__global__ void node_agg_kernel(float* __restrict__ out, int v) {
    __shared__ int   sh_s[8][32];
    __shared__ float sh_a[8][32][4];

    const int wid  = threadIdx.x >> 5;
    const int lane = threadIdx.x & 31;
    const int n = blockIdx.x * 8 + wid;
    if (n >= v) return;

    const int start = g_rowstart[n];
    const int degn  = g_deg[n];
    const float4 ed = *(const float4*)&g_edst[n * 4];
    const int head  = lane >> 3;

    float acc0 = 0.f, acc1 = 0.f;
    float d0 = 0.f, d1 = 0.f, d2 = 0.f, d3 = 0.f;

    for (int i0 = 0; i0 < degn; i0 += 32) {
        int idx = i0 + lane;
        int s = 0;
        float ex0 = 0.f, ex1 = 0.f, ex2 = 0.f, ex3 = 0.f;
        if (idx < degn) {
            s = __ldg(&g_csr_src[start + idx]);
            float4 es = *(const float4*)&g_esrc[s * 4];
            float w;
            w = es.x + ed.x; w = w > 0.f ? w : NEG_SLOPE * w; ex0 = __expf(w);
            w = es.y + ed.y; w = w > 0.f ? w : NEG_SLOPE * w; ex1 = __expf(w);
            w = es.z + ed.z; w = w > 0.f ? w : NEG_SLOPE * w; ex2 = __expf(w);
            w = es.w + ed.w; w = w > 0.f ? w : NEG_SLOPE * w; ex3 = __expf(w);
        }
        d0 += ex0; d1 += ex1; d2 += ex2; d3 += ex3;
        sh_s[wid][lane] = s;
        *(float4*)&sh_a[wid][lane][0] = make_float4(ex0, ex1, ex2, ex3);
        __syncwarp();

        int cnt = degn - i0; if (cnt > 32) cnt = 32;
        const float* zb = g_z + (size_t)lane * 2;
        int j = 0;
        for (; j + 8 <= cnt; j += 8) {
            int    sj[8];
            float2 zj[8];
            float  aj[8];
#pragma unroll
            for (int u = 0; u < 8; ++u) sj[u] = sh_s[wid][j + u];
#pragma unroll
            for (int u = 0; u < 8; ++u) zj[u] = *(const float2*)(zb + (size_t)sj[u] * HC);
#pragma unroll
            for (int u = 0; u < 8; ++u) aj[u] = sh_a[wid][j + u][head];
#pragma unroll
            for (int u = 0; u < 8; ++u) {
                acc0 += zj[u].x * aj[u];
                acc1 += zj[u].y * aj[u];
            }
        }
        for (; j < cnt; ++j) {
            int sj = sh_s[wid][j];
            float a = sh_a[wid][j][head];
            float2 zv = *(const float2*)(zb + (size_t)sj * HC);
            acc0 += zv.x * a; acc1 += zv.y * a;
        }
        __syncwarp();
    }

#pragma unroll
    for (int o = 16; o; o >>= 1) {
        d0 += __shfl_xor_sync(0xffffffffu, d0, o);
        d1 += __shfl_xor_sync(0xffffffffu, d1, o);
        d2 += __shfl_xor_sync(0xffffffffu, d2, o);
        d3 += __shfl_xor_sync(0xffffffffu, d3, o);
    }
    float den = head == 0 ? d0 : head == 1 ? d1 : head == 2 ? d2 : d3;
    float r = __frcp_rn(den + 1e-9f);
    acc0 *= r; acc1 *= r;
    acc0 = acc0 > 0.f ? acc0 : expm1f(acc0);
    acc1 = acc1 > 0.f ? acc1 : expm1f(acc1);
    *(float2*)&out[(size_t)n * HC + lane * 2] = make_float2(acc0, acc1);
}

// ---------------- launch ----------------
// gemm stays launch #4 so ncu keeps profiling it.
extern "C" void kernel_launch(void* const* d_in, const int* in_sizes, int n_in,
                              void* d_out, int out_size) {
    const float* x     = (const float*)d_in[0];
    const int*   ei    = (const int*)d_in[1];
    const float* W     = (const float*)d_in[2];
    const float* a_src = (const float*)d_in[3];
    const float* a_dst = (const float*)d_in[4];
    float* out = (float*)d_out;

    int v    = in_sizes[0] / IN_CH;
    int ecnt = in_sizes[1] / 2;
    int nb   = (v + SCAN_BLK - 1) / SCAN_BLK;

    const int smem = (IN_CH * HC + TROWS * 132 + 128) * sizeof(float); // ~98.5KB
    cudaFuncSetAttribute(gemm_logits_kernel,
                         cudaFuncAttributeMaxDynamicSharedMemorySize, smem);

    zero_deg_kernel<<<(v + 255) / 256, 256>>>(v);
    count_kernel<<<(ecnt + 255) / 256, 256>>>(ei, ecnt);
    scan1_kernel<<<nb, SCAN_BLK>>>(v);
    gemm_logits_kernel<<<(v + TROWS - 1) / TROWS, dim3(16, 32), smem>>>(x, W, a_src, a_dst, v);
    scan3_kernel<<<nb, SCAN_BLK>>>(v);
    scatter_kernel<<<(ecnt + 255) / 256, 256>>>(ei, ecnt);
    node_agg_kernel<<<(v + 7) / 8, 256>>>(out, v);
}

// round 11
// speedup vs baseline: 1.1817x; 1.0757x over previous
#include <cuda_runtime.h>
#include <math.h>

#define V_MAX   100000
#define E_MAX   1600000
#define IN_CH   128
#define HEADS   4
#define HC      64
#define NEG_SLOPE 0.2f
#define SCAN_BLK 256
#define GROWS   128             // gemm block tile rows
#define WPAD    72              // padded W smem row stride (bank-conflict-free)

// ---------------- scratch (device globals; no allocation) ----------------
__device__ float g_z[(size_t)V_MAX * HC];     // projected features  [V,64]
__device__ float g_esrc[V_MAX * HEADS];       // per-node src logits [V,4]
__device__ float g_edst[V_MAX * HEADS];       // per-node dst logits [V,4]
__device__ int   g_deg[V_MAX];                // in-degree per node
__device__ int   g_excl[V_MAX];               // block-local exclusive scan
__device__ int   g_bsums[512];                // per-block sums
__device__ int   g_rowstart[V_MAX];           // CSR row offsets
__device__ int   g_cursor[V_MAX];             // scatter cursors
__device__ int   g_csr_src[E_MAX];            // src node per CSR slot

// ---------------- CSR build ----------------
__global__ void zero_deg_kernel(int v) {
    int i = blockIdx.x * blockDim.x + threadIdx.x;
    if (i < v) g_deg[i] = 0;
}

__global__ void count_kernel(const int* __restrict__ ei, int ecnt) {
    int e = blockIdx.x * blockDim.x + threadIdx.x;
    if (e < ecnt) atomicAdd(&g_deg[ei[ecnt + e]], 1);
}

__global__ void scan1_kernel(int v) {
    __shared__ int sh[SCAN_BLK];
    int t = threadIdx.x;
    int i = blockIdx.x * SCAN_BLK + t;
    int val = (i < v) ? g_deg[i] : 0;
    sh[t] = val;
    __syncthreads();
#pragma unroll
    for (int off = 1; off < SCAN_BLK; off <<= 1) {
        int y = (t >= off) ? sh[t - off] : 0;
        __syncthreads();
        sh[t] += y;
        __syncthreads();
    }
    if (i < v) g_excl[i] = sh[t] - val;
    if (t == SCAN_BLK - 1) g_bsums[blockIdx.x] = sh[t];
}

__global__ void scan3_kernel(int v) {
    __shared__ int red[SCAN_BLK];
    const int b = blockIdx.x;
    const int t = threadIdx.x;
    int sum = 0;
    for (int i = t; i < b; i += SCAN_BLK) sum += g_bsums[i];
    red[t] = sum;
    __syncthreads();
#pragma unroll
    for (int off = SCAN_BLK / 2; off; off >>= 1) {
        if (t < off) red[t] += red[t + off];
        __syncthreads();
    }
    int prefix = red[0];
    int i = b * SCAN_BLK + t;
    if (i < v) {
        int r = g_excl[i] + prefix;
        g_rowstart[i] = r;
        g_cursor[i]   = r;
    }
}

__global__ void scatter_kernel(const int* __restrict__ ei, int ecnt) {
    int e = blockIdx.x * blockDim.x + threadIdx.x;
    if (e >= ecnt) return;
    int s = ei[e];
    int d = ei[ecnt + e];
    int pos = atomicAdd(&g_cursor[d], 1);
    g_csr_src[pos] = s;
}

// ---------------- helpers for tf32 mma ----------------
__device__ __forceinline__ unsigned cvt_tf32(float f) {
    unsigned u;
    asm("cvt.rna.tf32.f32 %0, %1;" : "=r"(u) : "f"(f));
    return u;
}

__device__ __forceinline__ void mma_tf32(float& c0, float& c1, float& c2, float& c3,
                                         unsigned a0, unsigned a1, unsigned a2, unsigned a3,
                                         unsigned b0, unsigned b1) {
    asm("mma.sync.aligned.m16n8k8.row.col.f32.tf32.tf32.f32 "
        "{%0,%1,%2,%3}, {%4,%5,%6,%7}, {%8,%9}, {%0,%1,%2,%3};"
        : "+f"(c0), "+f"(c1), "+f"(c2), "+f"(c3)
        : "r"(a0), "r"(a1), "r"(a2), "r"(a3), "r"(b0), "r"(b1));
}

// ---------------- fused GEMM + logits (tf32 tensor cores, 3xTF32) --------
// 256 threads = 8 warps; block tile 128 rows x 64 cols, K=128.
// Warp w owns rows [w*16, w*16+16), all 64 cols as 8 m16n8k8 n-tiles.
// W split into tf32 hi/lo in smem (stride 72: banks (8t+g) all distinct).
// A fragments loaded straight from global x (each element read once),
// split in registers. acc = Ahi*Bhi + Ahi*Blo + Alo*Bhi  (~fp32 accurate).
__global__ void __launch_bounds__(256, 2)
gemm_logits_kernel(const float* __restrict__ x,
                   const float* __restrict__ W,
                   const float* __restrict__ a_src,
                   const float* __restrict__ a_dst,
                   int v)
{
    extern __shared__ float sm[];
    float* Whi = sm;                        // 128 * 72
    float* Wlo = Whi + IN_CH * WPAD;        // 128 * 72
    float* as  = Wlo + IN_CH * WPAD;        // 64
    float* ad  = as + 64;                   // 64

    const int tid  = threadIdx.x;
    const int wid  = tid >> 5;
    const int lane = tid & 31;
    const int g = lane >> 2;               // group id 0..7
    const int t = lane & 3;                // thread-in-group 0..3
    const int row0 = blockIdx.x * GROWS;

    // stage W as tf32 hi/lo
    for (int i = tid; i < IN_CH * HC; i += 256) {
        int k = i >> 6, n = i & 63;
        float w = W[i];
        unsigned hu = cvt_tf32(w);
        float hf = __uint_as_float(hu);
        Whi[k * WPAD + n] = hf;
        Wlo[k * WPAD + n] = __uint_as_float(cvt_tf32(w - hf));
    }
    if (tid < 64)       as[tid]      = a_src[tid];
    else if (tid < 128) ad[tid - 64] = a_dst[tid - 64];
    __syncthreads();

    // accumulators: 8 n-tiles x {c0,c1 (row g), c2,c3 (row g+8)}
    float c0[8], c1[8], c2[8], c3[8];
#pragma unroll
    for (int nt = 0; nt < 8; ++nt) { c0[nt] = c1[nt] = c2[nt] = c3[nt] = 0.f; }

    const int r_lo = row0 + wid * 16 + g;
    const int r_hi = r_lo + 8;
    const bool vlo = r_lo < v, vhi = r_hi < v;
    const float* xlo = x + (size_t)r_lo * IN_CH;
    const float* xhi = x + (size_t)r_hi * IN_CH;

#pragma unroll 2
    for (int ks = 0; ks < IN_CH / 8; ++ks) {
        const int k0 = ks * 8;
        float a0f = vlo ? xlo[k0 + t]     : 0.f;
        float a1f = vhi ? xhi[k0 + t]     : 0.f;
        float a2f = vlo ? xlo[k0 + t + 4] : 0.f;
        float a3f = vhi ? xhi[k0 + t + 4] : 0.f;

        unsigned a0h = cvt_tf32(a0f), a1h = cvt_tf32(a1f);
        unsigned a2h = cvt_tf32(a2f), a3h = cvt_tf32(a3f);
        unsigned a0l = cvt_tf32(a0f - __uint_as_float(a0h));
        unsigned a1l = cvt_tf32(a1f - __uint_as_float(a1h));
        unsigned a2l = cvt_tf32(a2f - __uint_as_float(a2h));
        unsigned a3l = cvt_tf32(a3f - __uint_as_float(a3h));

        const int krow0 = (k0 + t) * WPAD;
        const int krow1 = (k0 + t + 4) * WPAD;
#pragma unroll
        for (int nt = 0; nt < 8; ++nt) {
            int col = nt * 8 + g;
            unsigned b0h = __float_as_uint(Whi[krow0 + col]);
            unsigned b1h = __float_as_uint(Whi[krow1 + col]);
            unsigned b0l = __float_as_uint(Wlo[krow0 + col]);
            unsigned b1l = __float_as_uint(Wlo[krow1 + col]);
            mma_tf32(c0[nt], c1[nt], c2[nt], c3[nt], a0h, a1h, a2h, a3h, b0h, b1h);
            mma_tf32(c0[nt], c1[nt], c2[nt], c3[nt], a0h, a1h, a2h, a3h, b0l, b1l);
            mma_tf32(c0[nt], c1[nt], c2[nt], c3[nt], a0l, a1l, a2l, a3l, b0h, b1h);
        }
    }

    // ---- epilogue: store z + per-node logits ----
    // thread holds cols nt*8 + 2t, +1 for rows r_lo (c0,c1) and r_hi (c2,c3)
    if (vlo) {
#pragma unroll
        for (int nt = 0; nt < 8; ++nt)
            *(float2*)&g_z[(size_t)r_lo * HC + nt * 8 + 2 * t] = make_float2(c0[nt], c1[nt]);
    }
    if (vhi) {
#pragma unroll
        for (int nt = 0; nt < 8; ++nt)
            *(float2*)&g_z[(size_t)r_hi * HC + nt * 8 + 2 * t] = make_float2(c2[nt], c3[nt]);
    }

#pragma unroll
    for (int h = 0; h < HEADS; ++h) {
        // head h covers cols h*16 .. h*16+15 == n-tiles 2h, 2h+1
        float s0 = as[h * 16 + 2 * t],     s1 = as[h * 16 + 2 * t + 1];
        float s2 = as[h * 16 + 8 + 2 * t], s3 = as[h * 16 + 8 + 2 * t + 1];
        float d0 = ad[h * 16 + 2 * t],     d1 = ad[h * 16 + 2 * t + 1];
        float d2 = ad[h * 16 + 8 + 2 * t], d3 = ad[h * 16 + 8 + 2 * t + 1];

        float psl = c0[2*h]*s0 + c1[2*h]*s1 + c0[2*h+1]*s2 + c1[2*h+1]*s3;
        float pdl = c0[2*h]*d0 + c1[2*h]*d1 + c0[2*h+1]*d2 + c1[2*h+1]*d3;
        float psh = c2[2*h]*s0 + c3[2*h]*s1 + c2[2*h+1]*s2 + c3[2*h+1]*s3;
        float pdh = c2[2*h]*d0 + c3[2*h]*d1 + c2[2*h+1]*d2 + c3[2*h+1]*d3;

        psl += __shfl_xor_sync(0xffffffffu, psl, 1);
        psl += __shfl_xor_sync(0xffffffffu, psl, 2);
        pdl += __shfl_xor_sync(0xffffffffu, pdl, 1);
        pdl += __shfl_xor_sync(0xffffffffu, pdl, 2);
        psh += __shfl_xor_sync(0xffffffffu, psh, 1);
        psh += __shfl_xor_sync(0xffffffffu, psh, 2);
        pdh += __shfl_xor_sync(0xffffffffu, pdh, 1);
        pdh += __shfl_xor_sync(0xffffffffu, pdh, 2);

        if (t == 0) {
            if (vlo) {
                g_esrc[r_lo * HEADS + h] = psl;
                g_edst[r_lo * HEADS + h] = pdl;
            }
            if (vhi) {
                g_esrc[r_hi * HEADS + h] = psh;
                g_edst[r_hi * HEADS + h] = pdh;
            }
        }
    }
}

// ---------------- fused softmax + aggregation (CSR, smem-staged) ----------
__global__ void node_agg_kernel(float* __restrict__ out, int v) {
    __shared__ int   sh_s[8][32];
    __shared__ float sh_a[8][32][4];

    const int wid  = threadIdx.x >> 5;
    const int lane = threadIdx.x & 31;
    const int n = blockIdx.x * 8 + wid;
    if (n >= v) return;

    const int start = g_rowstart[n];
    const int degn  = g_deg[n];
    const float4 ed = *(const float4*)&g_edst[n * 4];
    const int head  = lane >> 3;

    float acc0 = 0.f, acc1 = 0.f;
    float d0 = 0.f, d1 = 0.f, d2 = 0.f, d3 = 0.f;

    for (int i0 = 0; i0 < degn; i0 += 32) {
        int idx = i0 + lane;
        int s = 0;
        float ex0 = 0.f, ex1 = 0.f, ex2 = 0.f, ex3 = 0.f;
        if (idx < degn) {
            s = __ldg(&g_csr_src[start + idx]);
            float4 es = *(const float4*)&g_esrc[s * 4];
            float w;
            w = es.x + ed.x; w = w > 0.f ? w : NEG_SLOPE * w; ex0 = __expf(w);
            w = es.y + ed.y; w = w > 0.f ? w : NEG_SLOPE * w; ex1 = __expf(w);
            w = es.z + ed.z; w = w > 0.f ? w : NEG_SLOPE * w; ex2 = __expf(w);
            w = es.w + ed.w; w = w > 0.f ? w : NEG_SLOPE * w; ex3 = __expf(w);
        }
        d0 += ex0; d1 += ex1; d2 += ex2; d3 += ex3;
        sh_s[wid][lane] = s;
        *(float4*)&sh_a[wid][lane][0] = make_float4(ex0, ex1, ex2, ex3);
        __syncwarp();

        int cnt = degn - i0; if (cnt > 32) cnt = 32;
        const float* zb = g_z + (size_t)lane * 2;
        int j = 0;
        for (; j + 8 <= cnt; j += 8) {
            int    sj[8];
            float2 zj[8];
            float  aj[8];
#pragma unroll
            for (int u = 0; u < 8; ++u) sj[u] = sh_s[wid][j + u];
#pragma unroll
            for (int u = 0; u < 8; ++u) zj[u] = *(const float2*)(zb + (size_t)sj[u] * HC);
#pragma unroll
            for (int u = 0; u < 8; ++u) aj[u] = sh_a[wid][j + u][head];
#pragma unroll
            for (int u = 0; u < 8; ++u) {
                acc0 += zj[u].x * aj[u];
                acc1 += zj[u].y * aj[u];
            }
        }
        for (; j < cnt; ++j) {
            int sj = sh_s[wid][j];
            float a = sh_a[wid][j][head];
            float2 zv = *(const float2*)(zb + (size_t)sj * HC);
            acc0 += zv.x * a; acc1 += zv.y * a;
        }
        __syncwarp();
    }

#pragma unroll
    for (int o = 16; o; o >>= 1) {
        d0 += __shfl_xor_sync(0xffffffffu, d0, o);
        d1 += __shfl_xor_sync(0xffffffffu, d1, o);
        d2 += __shfl_xor_sync(0xffffffffu, d2, o);
        d3 += __shfl_xor_sync(0xffffffffu, d3, o);
    }
    float den = head == 0 ? d0 : head == 1 ? d1 : head == 2 ? d2 : d3;
    float r = __frcp_rn(den + 1e-9f);
    acc0 *= r; acc1 *= r;
    acc0 = acc0 > 0.f ? acc0 : expm1f(acc0);
    acc1 = acc1 > 0.f ? acc1 : expm1f(acc1);
    *(float2*)&out[(size_t)n * HC + lane * 2] = make_float2(acc0, acc1);
}

// ---------------- launch ----------------
// gemm stays launch #4 so ncu keeps profiling it.
extern "C" void kernel_launch(void* const* d_in, const int* in_sizes, int n_in,
                              void* d_out, int out_size) {
    const float* x     = (const float*)d_in[0];
    const int*   ei    = (const int*)d_in[1];
    const float* W     = (const float*)d_in[2];
    const float* a_src = (const float*)d_in[3];
    const float* a_dst = (const float*)d_in[4];
    float* out = (float*)d_out;

    int v    = in_sizes[0] / IN_CH;
    int ecnt = in_sizes[1] / 2;
    int nb   = (v + SCAN_BLK - 1) / SCAN_BLK;

    const int smem = (IN_CH * WPAD * 2 + 128) * sizeof(float); // ~74.2KB
    cudaFuncSetAttribute(gemm_logits_kernel,
                         cudaFuncAttributeMaxDynamicSharedMemorySize, smem);

    zero_deg_kernel<<<(v + 255) / 256, 256>>>(v);
    count_kernel<<<(ecnt + 255) / 256, 256>>>(ei, ecnt);
    scan1_kernel<<<nb, SCAN_BLK>>>(v);
    gemm_logits_kernel<<<(v + GROWS - 1) / GROWS, 256, smem>>>(x, W, a_src, a_dst, v);
    scan3_kernel<<<nb, SCAN_BLK>>>(v);
    scatter_kernel<<<(ecnt + 255) / 256, 256>>>(ei, ecnt);
    node_agg_kernel<<<(v + 7) / 8, 256>>>(out, v);
}

// round 12
// speedup vs baseline: 1.2982x; 1.0986x over previous
#include <cuda_runtime.h>
#include <math.h>

#define V_MAX   100000
#define E_MAX   1600000
#define IN_CH   128
#define HEADS   4
#define HC      64
#define NEG_SLOPE 0.2f
#define SCAN_BLK 256
#define GROWS   128
#define WPAD    72

// ---------------- scratch (device globals; no allocation) ----------------
__device__ float g_z[(size_t)V_MAX * HC];
__device__ float g_esrc[V_MAX * HEADS];
__device__ float g_edst[V_MAX * HEADS];
__device__ int   g_deg[V_MAX];
__device__ int   g_excl[V_MAX];
__device__ int   g_bsums[512];
__device__ int   g_rowstart[V_MAX];
__device__ int   g_cursor[V_MAX];
__device__ int   g_csr_src[E_MAX];

// ---------------- CSR build ----------------
__global__ void zero_deg_kernel(int v) {
    int i = blockIdx.x * blockDim.x + threadIdx.x;
    if (i < v) g_deg[i] = 0;
}

__global__ void count_kernel(const int* __restrict__ ei, int ecnt) {
    int e = blockIdx.x * blockDim.x + threadIdx.x;
    if (e < ecnt) atomicAdd(&g_deg[ei[ecnt + e]], 1);
}

__global__ void scan1_kernel(int v) {
    __shared__ int sh[SCAN_BLK];
    int t = threadIdx.x;
    int i = blockIdx.x * SCAN_BLK + t;
    int val = (i < v) ? g_deg[i] : 0;
    sh[t] = val;
    __syncthreads();
#pragma unroll
    for (int off = 1; off < SCAN_BLK; off <<= 1) {
        int y = (t >= off) ? sh[t - off] : 0;
        __syncthreads();
        sh[t] += y;
        __syncthreads();
    }
    if (i < v) g_excl[i] = sh[t] - val;
    if (t == SCAN_BLK - 1) g_bsums[blockIdx.x] = sh[t];
}

__global__ void scan3_kernel(int v) {
    __shared__ int red[SCAN_BLK];
    const int b = blockIdx.x;
    const int t = threadIdx.x;
    int sum = 0;
    for (int i = t; i < b; i += SCAN_BLK) sum += g_bsums[i];
    red[t] = sum;
    __syncthreads();
#pragma unroll
    for (int off = SCAN_BLK / 2; off; off >>= 1) {
        if (t < off) red[t] += red[t + off];
        __syncthreads();
    }
    int prefix = red[0];
    int i = b * SCAN_BLK + t;
    if (i < v) {
        int r = g_excl[i] + prefix;
        g_rowstart[i] = r;
        g_cursor[i]   = r;
    }
}

__global__ void scatter_kernel(const int* __restrict__ ei, int ecnt) {
    int e = blockIdx.x * blockDim.x + threadIdx.x;
    if (e >= ecnt) return;
    int s = ei[e];
    int d = ei[ecnt + e];
    int pos = atomicAdd(&g_cursor[d], 1);
    g_csr_src[pos] = s;
}

// ---------------- helpers for tf32 mma ----------------
__device__ __forceinline__ unsigned cvt_tf32(float f) {
    unsigned u;
    asm("cvt.rna.tf32.f32 %0, %1;" : "=r"(u) : "f"(f));
    return u;
}

__device__ __forceinline__ void mma_tf32(float& c0, float& c1, float& c2, float& c3,
                                         unsigned a0, unsigned a1, unsigned a2, unsigned a3,
                                         unsigned b0, unsigned b1) {
    asm("mma.sync.aligned.m16n8k8.row.col.f32.tf32.tf32.f32 "
        "{%0,%1,%2,%3}, {%4,%5,%6,%7}, {%8,%9}, {%0,%1,%2,%3};"
        : "+f"(c0), "+f"(c1), "+f"(c2), "+f"(c3)
        : "r"(a0), "r"(a1), "r"(a2), "r"(a3), "r"(b0), "r"(b1));
}

// ---------------- fused GEMM + logits (tf32, 3xTF32) — R11 proven --------
__global__ void __launch_bounds__(256, 2)
gemm_logits_kernel(const float* __restrict__ x,
                   const float* __restrict__ W,
                   const float* __restrict__ a_src,
                   const float* __restrict__ a_dst,
                   int v)
{
    extern __shared__ float sm[];
    float* Whi = sm;
    float* Wlo = Whi + IN_CH * WPAD;
    float* as  = Wlo + IN_CH * WPAD;
    float* ad  = as + 64;

    const int tid  = threadIdx.x;
    const int wid  = tid >> 5;
    const int lane = tid & 31;
    const int g = lane >> 2;
    const int t = lane & 3;
    const int row0 = blockIdx.x * GROWS;

    for (int i = tid; i < IN_CH * HC; i += 256) {
        int k = i >> 6, n = i & 63;
        float w = W[i];
        unsigned hu = cvt_tf32(w);
        float hf = __uint_as_float(hu);
        Whi[k * WPAD + n] = hf;
        Wlo[k * WPAD + n] = __uint_as_float(cvt_tf32(w - hf));
    }
    if (tid < 64)       as[tid]      = a_src[tid];
    else if (tid < 128) ad[tid - 64] = a_dst[tid - 64];
    __syncthreads();

    float c0[8], c1[8], c2[8], c3[8];
#pragma unroll
    for (int nt = 0; nt < 8; ++nt) { c0[nt] = c1[nt] = c2[nt] = c3[nt] = 0.f; }

    const int r_lo = row0 + wid * 16 + g;
    const int r_hi = r_lo + 8;
    const bool vlo = r_lo < v, vhi = r_hi < v;
    const float* xlo = x + (size_t)r_lo * IN_CH;
    const float* xhi = x + (size_t)r_hi * IN_CH;

#pragma unroll 2
    for (int ks = 0; ks < IN_CH / 8; ++ks) {
        const int k0 = ks * 8;
        float a0f = vlo ? xlo[k0 + t]     : 0.f;
        float a1f = vhi ? xhi[k0 + t]     : 0.f;
        float a2f = vlo ? xlo[k0 + t + 4] : 0.f;
        float a3f = vhi ? xhi[k0 + t + 4] : 0.f;

        unsigned a0h = cvt_tf32(a0f), a1h = cvt_tf32(a1f);
        unsigned a2h = cvt_tf32(a2f), a3h = cvt_tf32(a3f);
        unsigned a0l = cvt_tf32(a0f - __uint_as_float(a0h));
        unsigned a1l = cvt_tf32(a1f - __uint_as_float(a1h));
        unsigned a2l = cvt_tf32(a2f - __uint_as_float(a2h));
        unsigned a3l = cvt_tf32(a3f - __uint_as_float(a3h));

        const int krow0 = (k0 + t) * WPAD;
        const int krow1 = (k0 + t + 4) * WPAD;
#pragma unroll
        for (int nt = 0; nt < 8; ++nt) {
            int col = nt * 8 + g;
            unsigned b0h = __float_as_uint(Whi[krow0 + col]);
            unsigned b1h = __float_as_uint(Whi[krow1 + col]);
            unsigned b0l = __float_as_uint(Wlo[krow0 + col]);
            unsigned b1l = __float_as_uint(Wlo[krow1 + col]);
            mma_tf32(c0[nt], c1[nt], c2[nt], c3[nt], a0h, a1h, a2h, a3h, b0h, b1h);
            mma_tf32(c0[nt], c1[nt], c2[nt], c3[nt], a0h, a1h, a2h, a3h, b0l, b1l);
            mma_tf32(c0[nt], c1[nt], c2[nt], c3[nt], a0l, a1l, a2l, a3l, b0h, b1h);
        }
    }

    if (vlo) {
#pragma unroll
        for (int nt = 0; nt < 8; ++nt)
            *(float2*)&g_z[(size_t)r_lo * HC + nt * 8 + 2 * t] = make_float2(c0[nt], c1[nt]);
    }
    if (vhi) {
#pragma unroll
        for (int nt = 0; nt < 8; ++nt)
            *(float2*)&g_z[(size_t)r_hi * HC + nt * 8 + 2 * t] = make_float2(c2[nt], c3[nt]);
    }

#pragma unroll
    for (int h = 0; h < HEADS; ++h) {
        float s0 = as[h * 16 + 2 * t],     s1 = as[h * 16 + 2 * t + 1];
        float s2 = as[h * 16 + 8 + 2 * t], s3 = as[h * 16 + 8 + 2 * t + 1];
        float d0 = ad[h * 16 + 2 * t],     d1 = ad[h * 16 + 2 * t + 1];
        float d2 = ad[h * 16 + 8 + 2 * t], d3 = ad[h * 16 + 8 + 2 * t + 1];

        float psl = c0[2*h]*s0 + c1[2*h]*s1 + c0[2*h+1]*s2 + c1[2*h+1]*s3;
        float pdl = c0[2*h]*d0 + c1[2*h]*d1 + c0[2*h+1]*d2 + c1[2*h+1]*d3;
        float psh = c2[2*h]*s0 + c3[2*h]*s1 + c2[2*h+1]*s2 + c3[2*h+1]*s3;
        float pdh = c2[2*h]*d0 + c3[2*h]*d1 + c2[2*h+1]*d2 + c3[2*h+1]*d3;

        psl += __shfl_xor_sync(0xffffffffu, psl, 1);
        psl += __shfl_xor_sync(0xffffffffu, psl, 2);
        pdl += __shfl_xor_sync(0xffffffffu, pdl, 1);
        pdl += __shfl_xor_sync(0xffffffffu, pdl, 2);
        psh += __shfl_xor_sync(0xffffffffu, psh, 1);
        psh += __shfl_xor_sync(0xffffffffu, psh, 2);
        pdh += __shfl_xor_sync(0xffffffffu, pdh, 1);
        pdh += __shfl_xor_sync(0xffffffffu, pdh, 2);

        if (t == 0) {
            if (vlo) {
                g_esrc[r_lo * HEADS + h] = psl;
                g_edst[r_lo * HEADS + h] = pdl;
            }
            if (vhi) {
                g_esrc[r_hi * HEADS + h] = psh;
                g_edst[r_hi * HEADS + h] = pdh;
            }
        }
    }
}

// ---------------- fused softmax + aggregation (CSR, smem-staged) ----------
__global__ void node_agg_kernel(float* __restrict__ out, int v) {
    __shared__ int   sh_s[8][32];
    __shared__ float sh_a[8][32][4];

    const int wid  = threadIdx.x >> 5;
    const int lane = threadIdx.x & 31;
    const int n = blockIdx.x * 8 + wid;
    if (n >= v) return;

    const int start = g_rowstart[n];
    const int degn  = g_deg[n];
    const float4 ed = *(const float4*)&g_edst[n * 4];
    const int head  = lane >> 3;

    float acc0 = 0.f, acc1 = 0.f;
    float d0 = 0.f, d1 = 0.f, d2 = 0.f, d3 = 0.f;

    for (int i0 = 0; i0 < degn; i0 += 32) {
        int idx = i0 + lane;
        int s = 0;
        float ex0 = 0.f, ex1 = 0.f, ex2 = 0.f, ex3 = 0.f;
        if (idx < degn) {
            s = __ldg(&g_csr_src[start + idx]);
            float4 es = *(const float4*)&g_esrc[s * 4];
            float w;
            w = es.x + ed.x; w = w > 0.f ? w : NEG_SLOPE * w; ex0 = __expf(w);
            w = es.y + ed.y; w = w > 0.f ? w : NEG_SLOPE * w; ex1 = __expf(w);
            w = es.z + ed.z; w = w > 0.f ? w : NEG_SLOPE * w; ex2 = __expf(w);
            w = es.w + ed.w; w = w > 0.f ? w : NEG_SLOPE * w; ex3 = __expf(w);
        }
        d0 += ex0; d1 += ex1; d2 += ex2; d3 += ex3;
        sh_s[wid][lane] = s;
        *(float4*)&sh_a[wid][lane][0] = make_float4(ex0, ex1, ex2, ex3);
        __syncwarp();

        int cnt = degn - i0; if (cnt > 32) cnt = 32;
        const float* zb = g_z + (size_t)lane * 2;
        int j = 0;
        for (; j + 8 <= cnt; j += 8) {
            int    sj[8];
            float2 zj[8];
            float  aj[8];
#pragma unroll
            for (int u = 0; u < 8; ++u) sj[u] = sh_s[wid][j + u];
#pragma unroll
            for (int u = 0; u < 8; ++u) zj[u] = *(const float2*)(zb + (size_t)sj[u] * HC);
#pragma unroll
            for (int u = 0; u < 8; ++u) aj[u] = sh_a[wid][j + u][head];
#pragma unroll
            for (int u = 0; u < 8; ++u) {
                acc0 += zj[u].x * aj[u];
                acc1 += zj[u].y * aj[u];
            }
        }
        for (; j < cnt; ++j) {
            int sj = sh_s[wid][j];
            float a = sh_a[wid][j][head];
            float2 zv = *(const float2*)(zb + (size_t)sj * HC);
            acc0 += zv.x * a; acc1 += zv.y * a;
        }
        __syncwarp();
    }

#pragma unroll
    for (int o = 16; o; o >>= 1) {
        d0 += __shfl_xor_sync(0xffffffffu, d0, o);
        d1 += __shfl_xor_sync(0xffffffffu, d1, o);
        d2 += __shfl_xor_sync(0xffffffffu, d2, o);
        d3 += __shfl_xor_sync(0xffffffffu, d3, o);
    }
    float den = head == 0 ? d0 : head == 1 ? d1 : head == 2 ? d2 : d3;
    float r = __frcp_rn(den + 1e-9f);
    acc0 *= r; acc1 *= r;
    acc0 = acc0 > 0.f ? acc0 : expm1f(acc0);
    acc1 = acc1 > 0.f ? acc1 : expm1f(acc1);
    *(float2*)&out[(size_t)n * HC + lane * 2] = make_float2(acc0, acc1);
}

// ---------------- launch: fork-join overlap of CSR build and GEMM --------
// default stream:  gemm ─────────────────┐
// side stream s2:  zero→count→scan1→scan3→scatter ─┤
//                                        node_agg ─┘ (default stream)
// Stream/events created once on the first (uncaptured) correctness call;
// captured fork-join via events is the standard graph-capture pattern.
extern "C" void kernel_launch(void* const* d_in, const int* in_sizes, int n_in,
                              void* d_out, int out_size) {
    const float* x     = (const float*)d_in[0];
    const int*   ei    = (const int*)d_in[1];
    const float* W     = (const float*)d_in[2];
    const float* a_src = (const float*)d_in[3];
    const float* a_dst = (const float*)d_in[4];
    float* out = (float*)d_out;

    int v    = in_sizes[0] / IN_CH;
    int ecnt = in_sizes[1] / 2;
    int nb   = (v + SCAN_BLK - 1) / SCAN_BLK;

    static cudaStream_t s2 = nullptr;
    static cudaEvent_t evFork = nullptr, evJoin = nullptr;
    if (s2 == nullptr) {
        cudaStreamCreateWithFlags(&s2, cudaStreamNonBlocking);
        cudaEventCreateWithFlags(&evFork, cudaEventDisableTiming);
        cudaEventCreateWithFlags(&evJoin, cudaEventDisableTiming);
    }

    const int smem = (IN_CH * WPAD * 2 + 128) * sizeof(float);
    cudaFuncSetAttribute(gemm_logits_kernel,
                         cudaFuncAttributeMaxDynamicSharedMemorySize, smem);

    // fork: side stream joins the capture graph off the main stream
    cudaEventRecord(evFork, 0);
    cudaStreamWaitEvent(s2, evFork, 0);

    // CSR build chain on s2
    zero_deg_kernel<<<(v + 255) / 256, 256, 0, s2>>>(v);
    count_kernel<<<(ecnt + 255) / 256, 256, 0, s2>>>(ei, ecnt);
    scan1_kernel<<<nb, SCAN_BLK, 0, s2>>>(v);

    // GEMM on the main stream (concurrent with CSR build)
    gemm_logits_kernel<<<(v + GROWS - 1) / GROWS, 256, smem>>>(x, W, a_src, a_dst, v);

    scan3_kernel<<<nb, SCAN_BLK, 0, s2>>>(v);
    scatter_kernel<<<(ecnt + 255) / 256, 256, 0, s2>>>(ei, ecnt);

    // join: node_agg needs both gemm (stream order) and CSR (event)
    cudaEventRecord(evJoin, s2);
    cudaStreamWaitEvent(0, evJoin, 0);
    node_agg_kernel<<<(v + 7) / 8, 256>>>(out, v);
}